// round 8
// baseline (speedup 1.0000x reference)
#include <cuda_runtime.h>

#define D 256
#define BATCH 8
#define SEQ 1024
#define ROWS (BATCH*SEQ)
#define RT 32
#define GS 4            // positions per phi CTA (grid = 256)

typedef unsigned long long ull;

// Scratch (static device globals -- no allocation allowed)
__device__ float g_MT[2][D*D];        // M transposed: MT[k][i] = M[i][k]
__device__ float g_PT[2][D*D];        // P transposed: PT[j][i] = P[i][j]
__device__ float g_xt[ROWS*D];        // post GEMM+LN activations
__device__ float g_y[ROWS*D];         // layer-1 output

// ---- f32x2 helpers (sm_103a packed fp32 pipe) ------------------------------
__device__ __forceinline__ ull pk2(float a, float b) {
    ull r; asm("mov.b64 %0, {%1,%2};" : "=l"(r) : "f"(a), "f"(b)); return r;
}
__device__ __forceinline__ void upk2(float& lo, float& hi, ull v) {
    asm("mov.b64 {%0,%1}, %2;" : "=f"(lo), "=f"(hi) : "l"(v));
}
__device__ __forceinline__ void fma2(ull& d, ull a, ull b) {
    asm("fma.rn.f32x2 %0, %1, %2, %0;" : "+l"(d) : "l"(a), "l"(b));
}

// ---------------------------------------------------------------------------
// Prep: transpose M1,M2,P1,P2 -> g_MT[0],g_MT[1],g_PT[0],g_PT[1]
// ---------------------------------------------------------------------------
__global__ void prep_kernel(const float* __restrict__ M1, const float* __restrict__ M2,
                            const float* __restrict__ P1, const float* __restrict__ P2)
{
    __shared__ float tile[32][33];
    const float* src; float* dst;
    int z = blockIdx.z;
    if      (z == 0) { src = M1; dst = g_MT[0]; }
    else if (z == 1) { src = M2; dst = g_MT[1]; }
    else if (z == 2) { src = P1; dst = g_PT[0]; }
    else             { src = P2; dst = g_PT[1]; }

    int x = blockIdx.x * 32 + threadIdx.x;
    int y = blockIdx.y * 32 + threadIdx.y;
    #pragma unroll
    for (int r = 0; r < 32; r += 8)
        tile[threadIdx.y + r][threadIdx.x] = src[(y + r) * D + x];
    __syncthreads();
    x = blockIdx.y * 32 + threadIdx.x;
    y = blockIdx.x * 32 + threadIdx.y;
    #pragma unroll
    for (int r = 0; r < 32; r += 8)
        dst[(y + r) * D + x] = tile[threadIdx.x][threadIdx.y + r];
}

// ---------------------------------------------------------------------------
// Kernel A: g_xt = LayerNorm(X @ M^T) * g + b     (f32x2 mainloop)
// grid = ROWS/RT, 256 threads (thread = output column i), RT rows per CTA
// ---------------------------------------------------------------------------
__global__ __launch_bounds__(256)
void gemm_ln_kernel(const float* __restrict__ Xext, int layer,
                    const float* __restrict__ gw, const float* __restrict__ bw)
{
    __shared__ float sm[256 * 36];

    const float* X  = (layer == 0) ? Xext : g_y;
    const float* MT = g_MT[layer];

    const int tid = threadIdx.x;
    const int r0  = blockIdx.x * RT;

    for (int idx = tid; idx < RT * D; idx += 256) {
        int r = idx >> 8, k = idx & 255;
        sm[k * 36 + r] = X[(r0 + r) * D + k];
    }
    __syncthreads();

    ull acc[16];
    #pragma unroll
    for (int q = 0; q < 16; q++) acc[q] = 0ULL;

    const int i = tid;
    #pragma unroll 4
    for (int k = 0; k < D; k++) {
        float m = __ldg(&MT[k * D + i]);                  // coalesced
        ull mm = pk2(m, m);
        const ulonglong2* xp = (const ulonglong2*)&sm[k * 36];   // broadcast
        #pragma unroll
        for (int q = 0; q < 8; q++) {
            ulonglong2 v = xp[q];
            fma2(acc[2 * q],     v.x, mm);
            fma2(acc[2 * q + 1], v.y, mm);
        }
    }
    __syncthreads();

    #pragma unroll
    for (int q = 0; q < 16; q++) {
        float lo, hi; upk2(lo, hi, acc[q]);
        sm[(2 * q) * D + i]     = lo;
        sm[(2 * q + 1) * D + i] = hi;
    }
    __syncthreads();

    const int w = tid >> 5, lane = tid & 31;
    for (int rr = w; rr < RT; rr += 8) {
        float s1 = 0.f, s2 = 0.f;
        float v[8];
        #pragma unroll
        for (int u = 0; u < 8; u++) {
            v[u] = sm[rr * D + u * 32 + lane];
            s1 += v[u];
            s2 = fmaf(v[u], v[u], s2);
        }
        #pragma unroll
        for (int o = 16; o > 0; o >>= 1) {
            s1 += __shfl_xor_sync(0xffffffffu, s1, o);
            s2 += __shfl_xor_sync(0xffffffffu, s2, o);
        }
        float mu   = s1 * (1.0f / D);
        float var  = s2 * (1.0f / D) - mu * mu;
        float rstd = rsqrtf(var + 1e-5f);
        int row = r0 + rr;
        #pragma unroll
        for (int u = 0; u < 8; u++) {
            int col = u * 32 + lane;
            g_xt[row * D + col] =
                (v[u] - mu) * rstd * __ldg(&gw[col]) + __ldg(&bw[col]);
        }
    }
}

// ---------------------------------------------------------------------------
// Kernel B: out[b,s,i] = res[b,s,i] + sum_j xt[b,s,j]*P[i,j]*cos(2*pi*s/p(i,j))
// grid = SEQ/GS = 256 CTAs, 256 threads (thread = dim i), p = i*256+j+2.
// All per-(i,j) trig coefficients computed from p in registers:
//   r = rcp.approx(p) (MUFU, no memory), delta = 2*pi*r.
// Warps 1-7 (p >= 8194): theta0 = s0*delta <= 0.79 -> no range reduction;
//   cos(d)=1-d^2/2, sin(d)=d(1-d^2/6) exact to fp32 ulp; c1 by angle addition,
//   c2,c3 by Chebyshev. Warp 0 uses the generic frac+__cosf path (separate loop).
// Only memory in the mainloop: LDG.32 of P (256 KB table, mostly L1-resident)
// + 8 broadcast LDS.128.  xts layout [j][b*4+u], stride 36.
// ---------------------------------------------------------------------------
__global__ __launch_bounds__(256, 2)
void phi_kernel(const float* __restrict__ resext, float* __restrict__ outext, int layer)
{
    __shared__ float xts[D * 36];   // [j][b*4+u], stride 36 (36 KB)

    const float* TP  = g_PT[layer];
    const float* RES = (layer == 0) ? resext : g_y;
    float* OUT       = (layer == 0) ? g_y    : outext;

    const int s0  = blockIdx.x * GS;
    const int tid = threadIdx.x;

    // stage GS*8 rows at positions s0..s0+GS-1 -> xts[j*36 + b*4 + u]
    for (int idx = tid; idx < GS * BATCH * D; idx += 256) {
        int row = idx >> 8;             // 0..31 = b*4 + u
        int j   = idx & 255;
        int b   = row >> 2;
        int u   = row & 3;
        xts[j * 36 + b * 4 + u] = g_xt[((b << 10) + s0 + u) * D + j];
    }
    __syncthreads();

    ull acc[BATCH][2];                  // [b][u-pair]
    #pragma unroll
    for (int b = 0; b < BATCH; b++) { acc[b][0] = 0ULL; acc[b][1] = 0ULL; }

    const float TWO_PI = 6.283185307179586f;
    const float sf0 = (float)s0;
    const float sf1 = (float)(s0 + 1);
    const float sf2 = (float)(s0 + 2);
    const float sf3 = (float)(s0 + 3);

    float p = (float)(tid * D + 2);     // exact in fp32 (< 2^24)

    if (tid < 32) {
        // ---- generic path (warp 0: p in [2, 8449], needs range reduction) ----
        #pragma unroll 4
        for (int j = 0; j < D; j++) {
            float P = __ldg(&TP[(j << 8) + tid]);
            float r; asm("rcp.approx.f32 %0, %1;" : "=f"(r) : "f"(p));
            float t0 = sf0 * r;  t0 -= floorf(t0);
            float t1 = sf1 * r;  t1 -= floorf(t1);
            float t2 = sf2 * r;  t2 -= floorf(t2);
            float t3 = sf3 * r;  t3 -= floorf(t3);
            float c0 = __cosf(t0 * TWO_PI);
            float c1 = __cosf(t1 * TWO_PI);
            float c2 = __cosf(t2 * TWO_PI);
            float c3 = __cosf(t3 * TWO_PI);
            ull w01 = pk2(c0 * P, c1 * P);
            ull w23 = pk2(c2 * P, c3 * P);
            const ulonglong2* xb = (const ulonglong2*)&xts[j * 36];
            #pragma unroll
            for (int b = 0; b < BATCH; b++) {
                ulonglong2 v = xb[b];
                fma2(acc[b][0], v.x, w01);
                fma2(acc[b][1], v.y, w23);
            }
            p += 1.0f;
        }
    } else {
        // ---- fast path (warps 1-7: p >= 8194, delta <= 7.7e-4) ----
        #pragma unroll 4
        for (int j = 0; j < D; j++) {
            float P = __ldg(&TP[(j << 8) + tid]);
            float r; asm("rcp.approx.f32 %0, %1;" : "=f"(r) : "f"(p));
            float d  = TWO_PI * r;                       // delta
            float d2 = d * d;
            float cd = fmaf(d2, -0.5f, 1.0f);            // cos(delta), fp32-exact
            float sd = d * fmaf(d2, -(1.0f / 6.0f), 1.0f);  // sin(delta)
            float s0v, c0;
            __sincosf(sf0 * d, &s0v, &c0);               // theta0 <= 0.79 rad
            float c1 = fmaf(c0, cd, -(s0v * sd));        // angle addition
            float k2 = cd + cd;
            float c2 = fmaf(k2, c1, -c0);                // Chebyshev
            float c3 = fmaf(k2, c2, -c1);
            ull w01 = pk2(c0 * P, c1 * P);
            ull w23 = pk2(c2 * P, c3 * P);
            const ulonglong2* xb = (const ulonglong2*)&xts[j * 36];
            #pragma unroll
            for (int b = 0; b < BATCH; b++) {
                ulonglong2 v = xb[b];
                fma2(acc[b][0], v.x, w01);
                fma2(acc[b][1], v.y, w23);
            }
            p += 1.0f;
        }
    }

    #pragma unroll
    for (int b = 0; b < BATCH; b++) {
        #pragma unroll
        for (int q = 0; q < 2; q++) {
            float lo, hi; upk2(lo, hi, acc[b][q]);
            int off0 = ((b << 10) + s0 + 2 * q)     * D + tid;
            int off1 = ((b << 10) + s0 + 2 * q + 1) * D + tid;
            OUT[off0] = lo + RES[off0];
            OUT[off1] = hi + RES[off1];
        }
    }
}

// ---------------------------------------------------------------------------
extern "C" void kernel_launch(void* const* d_in, const int* in_sizes, int n_in,
                              void* d_out, int out_size)
{
    const float* seq = (const float*)d_in[0];
    const float* M1  = (const float*)d_in[1];
    const float* P1  = (const float*)d_in[2];
    const float* g1  = (const float*)d_in[3];
    const float* b1  = (const float*)d_in[4];
    const float* M2  = (const float*)d_in[5];
    const float* P2  = (const float*)d_in[6];
    const float* g2  = (const float*)d_in[7];
    const float* b2  = (const float*)d_in[8];
    float* out = (float*)d_out;

    prep_kernel<<<dim3(8, 8, 4), dim3(32, 8)>>>(M1, M2, P1, P2);

    // layer 1
    gemm_ln_kernel<<<ROWS / RT, 256>>>(seq, 0, g1, b1);
    phi_kernel<<<SEQ / GS, 256>>>(seq, nullptr, 0);

    // layer 2
    gemm_ln_kernel<<<ROWS / RT, 256>>>(nullptr, 1, g2, b2);
    phi_kernel<<<SEQ / GS, 256>>>(nullptr, out, 1);
}

// round 12
// speedup vs baseline: 1.2007x; 1.2007x over previous
#include <cuda_runtime.h>

#define D 256
#define BATCH 8
#define SEQ 1024
#define ROWS (BATCH*SEQ)
#define RT 32
#define GS 4            // positions per phi CTA (grid = 256)

typedef unsigned long long ull;

// Scratch (static device globals -- no allocation allowed)
__device__ float  g_MT[2][D*D];        // M transposed: MT[k][i] = M[i][k]
__device__ float4 g_tbl[2][D*D];       // tbl[l][j*256+i] = (P[i][j], 1/p, sin(2pi/p), 2cos(2pi/p))
__device__ float  g_xt[ROWS*D];        // post GEMM+LN activations
__device__ float  g_y[ROWS*D];         // layer-1 output

// ---- f32x2 helpers (sm_103a packed fp32 pipe) ------------------------------
__device__ __forceinline__ ull pk2(float a, float b) {
    ull r; asm("mov.b64 %0, {%1,%2};" : "=l"(r) : "f"(a), "f"(b)); return r;
}
__device__ __forceinline__ void upk2(float& lo, float& hi, ull v) {
    asm("mov.b64 {%0,%1}, %2;" : "=f"(lo), "=f"(hi) : "l"(v));
}
__device__ __forceinline__ void fma2(ull& d, ull a, ull b) {
    asm("fma.rn.f32x2 %0, %1, %2, %0;" : "+l"(d) : "l"(a), "l"(b));
}

// ---------------------------------------------------------------------------
// Prep 1: transpose M1/M2 -> g_MT
// ---------------------------------------------------------------------------
__global__ void prep_mt_kernel(const float* __restrict__ M1, const float* __restrict__ M2)
{
    __shared__ float tile[32][33];
    const float* src = (blockIdx.z == 0) ? M1 : M2;
    float* dst = g_MT[blockIdx.z];

    int x = blockIdx.x * 32 + threadIdx.x;
    int y = blockIdx.y * 32 + threadIdx.y;
    #pragma unroll
    for (int r = 0; r < 32; r += 8)
        tile[threadIdx.y + r][threadIdx.x] = src[(y + r) * D + x];
    __syncthreads();
    x = blockIdx.y * 32 + threadIdx.x;
    y = blockIdx.x * 32 + threadIdx.y;
    #pragma unroll
    for (int r = 0; r < 32; r += 8)
        dst[(y + r) * D + x] = tile[threadIdx.x][threadIdx.y + r];
}

// ---------------------------------------------------------------------------
// Prep 2: fused table: g_tbl[l][j*256+i] = (P[i][j], 1/p, sin(2pi/p), 2cos(2pi/p))
// p = i*256 + j + 2
// ---------------------------------------------------------------------------
__global__ void prep_tbl_kernel(const float* __restrict__ P1, const float* __restrict__ P2)
{
    __shared__ float tile[32][33];
    const float* src = (blockIdx.z == 0) ? P1 : P2;
    float4* dst = g_tbl[blockIdx.z];

    int x = blockIdx.x * 32 + threadIdx.x;   // col j of P
    int y = blockIdx.y * 32 + threadIdx.y;   // row i of P
    #pragma unroll
    for (int r = 0; r < 32; r += 8)
        tile[threadIdx.y + r][threadIdx.x] = src[(y + r) * D + x];
    __syncthreads();
    int i = blockIdx.y * 32 + threadIdx.x;   // output col = i
    #pragma unroll
    for (int r = 0; r < 32; r += 8) {
        int j = blockIdx.x * 32 + threadIdx.y + r;
        float p    = (float)(i * D + j + 2);      // exact in fp32 (< 2^24)
        float rinv = 1.0f / p;
        float sd   = sinpif(2.0f * rinv);         // sin(2*pi/p), ~1 ulp
        float k2   = 2.0f * cospif(2.0f * rinv);  // 2*cos(2*pi/p)
        dst[(j << 8) + i] = make_float4(tile[threadIdx.x][threadIdx.y + r], rinv, sd, k2);
    }
}

// ---------------------------------------------------------------------------
// Kernel A: g_xt = LayerNorm(X @ M^T) * g + b
// grid = ROWS/RT, 256 threads. Thread tile = 4 adjacent cols x 8 rows:
//   per k: 1x LDG.128 of M (warp: 512B contiguous, 4 wf)
//        + 2x broadcast LDS.128 (row group warp-uniform, 2 wf)
//        + 16x fma2   -> L1 wavefronts 9 -> 6, fma pipe becomes binding.
// ---------------------------------------------------------------------------
__global__ __launch_bounds__(256, 2)
void gemm_ln_kernel(const float* __restrict__ Xext, int layer,
                    const float* __restrict__ gw, const float* __restrict__ bw)
{
    __shared__ float sm[256 * 36];   // phase 1/2: [k][r] stride 36; phase 3/4: [r][i]

    const float* X  = (layer == 0) ? Xext : g_y;
    const float* MT = g_MT[layer];

    const int tid = threadIdx.x;
    const int rg  = tid >> 6;          // row group: rows 8*rg .. 8*rg+7
    const int c4  = tid & 63;          // column quad: cols 4*c4 .. 4*c4+3
    const int r0  = blockIdx.x * RT;

    for (int idx = tid; idx < RT * D; idx += 256) {
        int r = idx >> 8, k = idx & 255;
        sm[k * 36 + r] = X[(r0 + r) * D + k];
    }
    __syncthreads();

    ull acc[4][4];                     // [c][row-pair]
    #pragma unroll
    for (int c = 0; c < 4; c++)
        #pragma unroll
        for (int q = 0; q < 4; q++) acc[c][q] = 0ULL;

    const float4* M4 = (const float4*)MT;        // M4[k*64 + c4]
    const int rbase = rg * 8;

    #pragma unroll 4
    for (int k = 0; k < D; k++) {
        float4 m = __ldg(&M4[k * 64 + c4]);                      // LDG.128 coalesced
        const ulonglong2* xp = (const ulonglong2*)&sm[k * 36 + rbase];  // 16B aligned
        ulonglong2 v0 = xp[0];         // rows rbase..rbase+3 (2 packed pairs)
        ulonglong2 v1 = xp[1];         // rows rbase+4..rbase+7
        ull m0 = pk2(m.x, m.x), m1 = pk2(m.y, m.y);
        ull m2 = pk2(m.z, m.z), m3 = pk2(m.w, m.w);
        fma2(acc[0][0], v0.x, m0); fma2(acc[0][1], v0.y, m0);
        fma2(acc[0][2], v1.x, m0); fma2(acc[0][3], v1.y, m0);
        fma2(acc[1][0], v0.x, m1); fma2(acc[1][1], v0.y, m1);
        fma2(acc[1][2], v1.x, m1); fma2(acc[1][3], v1.y, m1);
        fma2(acc[2][0], v0.x, m2); fma2(acc[2][1], v0.y, m2);
        fma2(acc[2][2], v1.x, m2); fma2(acc[2][3], v1.y, m2);
        fma2(acc[3][0], v0.x, m3); fma2(acc[3][1], v0.y, m3);
        fma2(acc[3][2], v1.x, m3); fma2(acc[3][3], v1.y, m3);
    }
    __syncthreads();

    // scatter to [r][i] layout: per row-pair assemble float4 over the 4 cols
    #pragma unroll
    for (int q = 0; q < 4; q++) {
        float lo0, hi0, lo1, hi1, lo2, hi2, lo3, hi3;
        upk2(lo0, hi0, acc[0][q]);
        upk2(lo1, hi1, acc[1][q]);
        upk2(lo2, hi2, acc[2][q]);
        upk2(lo3, hi3, acc[3][q]);
        ((float4*)&sm[(rbase + 2 * q)     * D])[c4] = make_float4(lo0, lo1, lo2, lo3);
        ((float4*)&sm[(rbase + 2 * q + 1) * D])[c4] = make_float4(hi0, hi1, hi2, hi3);
    }
    __syncthreads();

    const int w = tid >> 5, lane = tid & 31;
    for (int rr = w; rr < RT; rr += 8) {
        float s1 = 0.f, s2 = 0.f;
        float v[8];
        #pragma unroll
        for (int u = 0; u < 8; u++) {
            v[u] = sm[rr * D + u * 32 + lane];
            s1 += v[u];
            s2 = fmaf(v[u], v[u], s2);
        }
        #pragma unroll
        for (int o = 16; o > 0; o >>= 1) {
            s1 += __shfl_xor_sync(0xffffffffu, s1, o);
            s2 += __shfl_xor_sync(0xffffffffu, s2, o);
        }
        float mu   = s1 * (1.0f / D);
        float var  = s2 * (1.0f / D) - mu * mu;
        float rstd = rsqrtf(var + 1e-5f);
        int row = r0 + rr;
        #pragma unroll
        for (int u = 0; u < 8; u++) {
            int col = u * 32 + lane;
            g_xt[row * D + col] =
                (v[u] - mu) * rstd * __ldg(&gw[col]) + __ldg(&bw[col]);
        }
    }
}

// ---------------------------------------------------------------------------
// Kernel B (R7 best version): out = res + sum_j xt*P[i,j]*cos(2*pi*s/p(i,j))
// grid = SEQ/GS = 256 CTAs, 256 threads (thread = dim i).
// One __sincosf per j; c1 via angle addition (sinδ, k2=2cosδ from table);
// c2,c3 via Chebyshev. Warps 1-7 skip range reduction (t = s/p < 1 there).
// xts layout [j][b*4+u], row stride 36 floats: LDS.128 = 4 positions of one b.
// ---------------------------------------------------------------------------
__global__ __launch_bounds__(256, 2)
void phi_kernel(const float* __restrict__ resext, float* __restrict__ outext, int layer)
{
    __shared__ float xts[D * 36];   // [j][b*4+u], stride 36 (36 KB)

    const float4* TB = g_tbl[layer];
    const float* RES = (layer == 0) ? resext : g_y;
    float* OUT       = (layer == 0) ? g_y    : outext;

    const int s0  = blockIdx.x * GS;
    const int tid = threadIdx.x;

    for (int idx = tid; idx < GS * BATCH * D; idx += 256) {
        int row = idx >> 8;             // 0..31 = b*4 + u
        int j   = idx & 255;
        int b   = row >> 2;
        int u   = row & 3;
        xts[j * 36 + b * 4 + u] = g_xt[((b << 10) + s0 + u) * D + j];
    }
    __syncthreads();

    ull acc[BATCH][2];                  // [b][u-pair]
    #pragma unroll
    for (int b = 0; b < BATCH; b++) { acc[b][0] = 0ULL; acc[b][1] = 0ULL; }

    const float TWO_PI = 6.283185307179586f;
    const float sf0 = (float)s0;
    const bool  gen = (tid < 32);       // warp 0: may need range reduction

    #pragma unroll 4
    for (int j = 0; j < D; j++) {
        float4 tb = __ldg(&TB[(j << 8) + tid]);   // (P, 1/p, sin d, 2cos d)
        float t0 = sf0 * tb.y;
        if (gen) t0 -= floorf(t0);                // warp-uniform branch
        float s0v, c0;
        __sincosf(t0 * TWO_PI, &s0v, &c0);
        float c1 = fmaf(0.5f * tb.w, c0, -(s0v * tb.z));   // cos(theta + d)
        float c2 = fmaf(tb.w, c1, -c0);                    // Chebyshev
        float c3 = fmaf(tb.w, c2, -c1);

        ull w01 = pk2(c0 * tb.x, c1 * tb.x);
        ull w23 = pk2(c2 * tb.x, c3 * tb.x);

        const ulonglong2* xb = (const ulonglong2*)&xts[j * 36];  // 16B aligned
        #pragma unroll
        for (int b = 0; b < BATCH; b++) {
            ulonglong2 v = xb[b];      // (u0,u1 | u2,u3) for batch b, broadcast
            fma2(acc[b][0], v.x, w01);
            fma2(acc[b][1], v.y, w23);
        }
    }

    #pragma unroll
    for (int b = 0; b < BATCH; b++) {
        #pragma unroll
        for (int q = 0; q < 2; q++) {
            float lo, hi; upk2(lo, hi, acc[b][q]);
            int off0 = ((b << 10) + s0 + 2 * q)     * D + tid;
            int off1 = ((b << 10) + s0 + 2 * q + 1) * D + tid;
            OUT[off0] = lo + RES[off0];
            OUT[off1] = hi + RES[off1];
        }
    }
}

// ---------------------------------------------------------------------------
extern "C" void kernel_launch(void* const* d_in, const int* in_sizes, int n_in,
                              void* d_out, int out_size)
{
    const float* seq = (const float*)d_in[0];
    const float* M1  = (const float*)d_in[1];
    const float* P1  = (const float*)d_in[2];
    const float* g1  = (const float*)d_in[3];
    const float* b1  = (const float*)d_in[4];
    const float* M2  = (const float*)d_in[5];
    const float* P2  = (const float*)d_in[6];
    const float* g2  = (const float*)d_in[7];
    const float* b2  = (const float*)d_in[8];
    float* out = (float*)d_out;

    prep_mt_kernel <<<dim3(8, 8, 2), dim3(32, 8)>>>(M1, M2);
    prep_tbl_kernel<<<dim3(8, 8, 2), dim3(32, 8)>>>(P1, P2);

    // layer 1
    gemm_ln_kernel<<<ROWS / RT, 256>>>(seq, 0, g1, b1);
    phi_kernel<<<SEQ / GS, 256>>>(seq, nullptr, 0);

    // layer 2
    gemm_ln_kernel<<<ROWS / RT, 256>>>(nullptr, 1, g2, b2);
    phi_kernel<<<SEQ / GS, 256>>>(nullptr, out, 1);
}